// round 4
// baseline (speedup 1.0000x reference)
#include <cuda_runtime.h>
#include <math.h>

#define B_  32
#define G_  50
#define NC_ 80
#define NA_ 8400

// ---------------- device scratch ----------------
__device__ float4        g_box [B_*NA_];       // decoded cx,cy,w,h
__device__ float         g_obj [B_*NA_];
__device__ float         g_q   [NC_*B_*NA_];   // class-major planes: q = -log(pv)+log1p(-pv)-s (fg only)
__device__ int           g_flist[B_*NA_];      // compacted fg anchor ids (unordered)
__device__ int           g_nfg [B_];
__device__ float         g_cost[B_*G_*NA_];
__device__ float         g_ioum[B_*G_*NA_];
__device__ float         g_gtbox[B_*G_*4];
__device__ int           g_gtcls[B_*G_];
__device__ unsigned char g_gtval[B_*G_];
__device__ float         g_thr [B_*G_];
__device__ double        g_accb[B_][4];        // iou, obj, cls, numfg

__device__ __forceinline__ void anchor_map(int a, int& hw, int& W, int& HW, float& st) {
    if (a < 6400)      { hw = a;        W = 80; HW = 6400; st = 8.f;  }
    else if (a < 8000) { hw = a - 6400; W = 40; HW = 1600; st = 16.f; }
    else               { hw = a - 8000; W = 20; HW = 400;  st = 32.f; }
}

__device__ __forceinline__ float bce_logit(float x, float y) {
    return fmaxf(x, 0.f) - x * y + log1pf(expf(-fabsf(x)));
}

// ---------------- K1: gt extraction + zero ----------------
__global__ void k_gt(const float* __restrict__ labels) {
    int i = blockIdx.x * blockDim.x + threadIdx.x;
    if (i < B_ * 4) ((double*)g_accb)[i] = 0.0;
    if (i < B_) g_nfg[i] = 0;
    if (i >= B_ * G_) return;
    const float* l = labels + i * 5;
    float c = l[0], x = l[1], y = l[2], w = l[3], h = l[4];
    g_gtval[i] = (c + x + y + w + h) > 0.f;
    g_gtbox[i*4+0] = x; g_gtbox[i*4+1] = y; g_gtbox[i*4+2] = w; g_gtbox[i*4+3] = h;
    g_gtcls[i] = (int)c;
}

// ---------------- K2: decode + fg + compact + q planes + obj softplus ----------------
__global__ void k_decode(const float* __restrict__ out0,
                         const float* __restrict__ out1,
                         const float* __restrict__ out2) {
    __shared__ float sgt[G_*4];
    __shared__ unsigned char sval[G_];
    int b = blockIdx.y;
    if (threadIdx.x < G_*4) sgt[threadIdx.x] = g_gtbox[b*G_*4 + threadIdx.x];
    if (threadIdx.x < G_)   sval[threadIdx.x] = g_gtval[b*G_ + threadIdx.x];
    __syncthreads();

    int a = blockIdx.x * blockDim.x + threadIdx.x;
    int lane = threadIdx.x & 31;
    float softplus_obj = 0.f;
    bool fg = false;
    int idx = b * NA_ + a;
    float Bo = 0.f;
    const float* p = nullptr;
    int HW = 0;

    if (a < NA_) {
        int hw, W; float st;
        anchor_map(a, hw, W, HW, st);
        const float* src = (a < 6400) ? out0 : (a < 8000) ? out1 : out2;
        p = src + (size_t)b * 85 * HW + hw;

        float tx = p[0], ty = p[HW], tw = p[2*HW], th = p[3*HW], to = p[4*HW];
        int h = hw / W, w = hw - h * W;
        g_box[idx] = make_float4((tx + (float)w) * st, (ty + (float)h) * st,
                                 expf(tw) * st, expf(th) * st);
        g_obj[idx] = to;
        Bo = 1.f + expf(-to);
        softplus_obj = fmaxf(to, 0.f) + log1pf(expf(-fabsf(to)));

        float cx = ((float)w + 0.5f) * st, cy = ((float)h + 0.5f) * st;
        float rs = 2.5f * st;
        for (int g = 0; g < G_; g++) {
            if (!sval[g]) continue;
            float gx = sgt[g*4], gy = sgt[g*4+1], gw = sgt[g*4+2], gh = sgt[g*4+3];
            bool ib = (cx > gx - 0.5f*gw) && (cx < gx + 0.5f*gw) &&
                      (cy > gy - 0.5f*gh) && (cy < gy + 0.5f*gh);
            bool ic = (fabsf(cx - gx) < rs) && (fabsf(cy - gy) < rs);
            fg |= (ib | ic);
        }
    }

    // warp-aggregated compaction append
    unsigned bal = __ballot_sync(0xffffffffu, fg);
    if (bal) {
        int leader = __ffs(bal) - 1;
        int base = 0;
        if (lane == leader) base = atomicAdd(&g_nfg[b], __popc(bal));
        base = __shfl_sync(0xffffffffu, base, leader);
        if (fg) g_flist[b*NA_ + base + __popc(bal & ((1u << lane) - 1))] = a;
    }

    if (fg) {
        // per-class q = -log(pv) + log1p(-pv); accumulate s; write q - s planes
        float tc[NC_];
        float s = 0.f;
        #pragma unroll 8
        for (int c = 0; c < NC_; c++) {
            float xc = p[(5 + c) * HW];
            float pv = rsqrtf((1.f + expf(-xc)) * Bo);
            pv = fminf(fmaxf(pv, 1e-7f), 1.f - 1e-6f);
            float l1 = log1pf(-pv);
            s += l1;
            tc[c] = -logf(pv) + l1;
        }
        #pragma unroll 8
        for (int c = 0; c < NC_; c++)
            g_q[(size_t)c * (B_*NA_) + idx] = tc[c] - s;
    }

    // block-reduce softplus_obj
    #pragma unroll
    for (int off = 16; off; off >>= 1)
        softplus_obj += __shfl_down_sync(0xffffffffu, softplus_obj, off);
    __shared__ float swsum[8];
    int wid = threadIdx.x >> 5;
    if (lane == 0) swsum[wid] = softplus_obj;
    __syncthreads();
    if (threadIdx.x == 0) {
        float t = 0.f;
        for (int i = 0; i < 8; i++) t += swsum[i];
        atomicAdd(&g_accb[b][1], (double)t);
    }
}

// ---------------- K3: pair-parallel cost/iou ----------------
__global__ void k_cost() {
    int b = blockIdx.z, g = blockIdx.y;
    int gi = b * G_ + g;
    if (!g_gtval[gi]) return;
    int f = blockIdx.x * blockDim.x + threadIdx.x;
    if (f >= g_nfg[b]) return;

    int a = g_flist[b*NA_ + f];
    int idx = b * NA_ + a;
    float4 bb = g_box[idx];

    float gx = g_gtbox[gi*4+0], gy = g_gtbox[gi*4+1];
    float gw = g_gtbox[gi*4+2], gh = g_gtbox[gi*4+3];

    float bz2 = bb.z * 0.5f, bw2 = bb.w * 0.5f;
    float tlx = fmaxf(gx - gw*0.5f, bb.x - bz2);
    float tly = fmaxf(gy - gh*0.5f, bb.y - bw2);
    float brx = fminf(gx + gw*0.5f, bb.x + bz2);
    float bry = fminf(gy + gh*0.5f, bb.y + bw2);
    float en  = (tlx < brx && tly < bry) ? 1.f : 0.f;
    float inter = (brx - tlx) * (bry - tly) * en;
    float iou = inter / (gw*gh + bb.z*bb.w - inter + 1e-12f);

    int hw, W, HW; float st;
    anchor_map(a, hw, W, HW, st);
    int h = hw / W, w = hw - h * W;
    float cx = ((float)w + 0.5f) * st, cy = ((float)h + 0.5f) * st;
    bool ib = (cx > gx - 0.5f*gw) && (cx < gx + 0.5f*gw) &&
              (cy > gy - 0.5f*gh) && (cy < gy + 0.5f*gh);
    float rs = 2.5f * st;
    bool ic = (fabsf(cx - gx) < rs) && (fabsf(cy - gy) < rs);
    bool geom = ib && ic;

    float q = g_q[(size_t)g_gtcls[gi] * (B_*NA_) + idx];
    float cost = q - 3.f * logf(iou + 1e-8f) + (geom ? 0.f : 100000.f);

    int row = gi * NA_;
    g_cost[row + f] = cost;
    g_ioum[row + f] = iou;
}

// ---------------- K4: per (b,g): dyn_k and threshold ----------------
__global__ void k_topk() {
    int gwarp = (blockIdx.x * blockDim.x + threadIdx.x) >> 5;
    int lane = threadIdx.x & 31;
    if (gwarp >= B_ * G_) return;
    int b = gwarp / G_;
    if (!g_gtval[gwarp]) return;
    int N = g_nfg[b];
    if (N == 0) return;
    const float* crow = g_cost + (size_t)gwarp * NA_;
    const float* irow = g_ioum + (size_t)gwarp * NA_;

    float lc[10], li[10];
    #pragma unroll
    for (int i = 0; i < 10; i++) { lc[i] = 3.0e38f; li[i] = 0.f; }

    for (int a = lane; a < N; a += 32) {
        float c = crow[a];
        if (c < lc[9]) {
            int j = 9;
            while (j > 0 && lc[j-1] > c) { lc[j] = lc[j-1]; j--; }
            lc[j] = c;
        }
        float v = irow[a];
        if (v > li[9]) {
            int j = 9;
            while (j > 0 && li[j-1] < v) { li[j] = li[j-1]; j--; }
            li[j] = v;
        }
    }

    float isum = 0.f;
    {
        int ptr = 0; float head = li[0];
        for (int k = 0; k < 10; k++) {
            float bv = head; int bl = lane;
            #pragma unroll
            for (int off = 16; off; off >>= 1) {
                float ov = __shfl_down_sync(0xffffffffu, bv, off);
                int   ol = __shfl_down_sync(0xffffffffu, bl, off);
                if (ov > bv || (ov == bv && ol < bl)) { bv = ov; bl = ol; }
            }
            bv = __shfl_sync(0xffffffffu, bv, 0);
            bl = __shfl_sync(0xffffffffu, bl, 0);
            if (lane == bl) { ptr++; head = (ptr < 10) ? li[ptr] : -3.0e38f; }
            isum += bv;
        }
    }
    int dynk = (int)isum;
    if (dynk < 1) dynk = 1;
    if (dynk > 10) dynk = 10;
    if (dynk > N) dynk = N;

    float thr = 0.f;
    {
        int ptr = 0; float head = lc[0];
        for (int k = 0; k < 10; k++) {
            float bv = head; int bl = lane;
            #pragma unroll
            for (int off = 16; off; off >>= 1) {
                float ov = __shfl_down_sync(0xffffffffu, bv, off);
                int   ol = __shfl_down_sync(0xffffffffu, bl, off);
                if (ov < bv || (ov == bv && ol < bl)) { bv = ov; bl = ol; }
            }
            bv = __shfl_sync(0xffffffffu, bv, 0);
            bl = __shfl_sync(0xffffffffu, bl, 0);
            if (lane == bl) { ptr++; head = (ptr < 10) ? lc[ptr] : 3.0e38f; }
            if (k == dynk - 1) thr = bv;
        }
    }
    if (lane == 0) g_thr[gwarp] = thr;
}

// ---------------- K5: resolve + losses ----------------
__global__ void k_resolve(const float* __restrict__ out0,
                          const float* __restrict__ out1,
                          const float* __restrict__ out2) {
    __shared__ float sthr[G_];
    __shared__ unsigned char sval[G_];
    int b = blockIdx.y;
    if (threadIdx.x < G_) {
        sthr[threadIdx.x] = g_thr[b*G_ + threadIdx.x];
        sval[threadIdx.x] = g_gtval[b*G_ + threadIdx.x];
    }
    __syncthreads();

    int f = blockIdx.x * blockDim.x + threadIdx.x;
    float liou = 0.f, lobj = 0.f, lcls = 0.f, lfg = 0.f;
    if (f < g_nfg[b]) {
        int a = g_flist[b*NA_ + f];
        int idx = b * NA_ + a;
        unsigned long long mask = 0ull;
        int count = 0, bestg = 0;
        float minc = 3.4e38f;
        for (int g = 0; g < G_; g++) {
            if (!sval[g]) continue;
            float c = __ldg(&g_cost[(b*G_ + g) * NA_ + f]);
            if (c < minc) { minc = c; bestg = g; }
            if (c <= sthr[g]) { mask |= 1ull << g; count++; }
        }
        if (count > 1) mask &= (1ull << bestg);
        if (mask != 0ull) {
            int mg = __ffsll((long long)mask) - 1;
            float piou = 0.f;
            unsigned long long mm = mask;
            while (mm) {
                int g = __ffsll((long long)mm) - 1;
                mm &= mm - 1;
                piou += g_ioum[(b*G_ + g) * NA_ + f];
            }
            lfg = 1.f;
            lobj = -g_obj[idx];   // softplus part already accumulated over all anchors

            float4 bb = g_box[idx];
            int gi = b * G_ + mg;
            float gx = g_gtbox[gi*4+0], gy = g_gtbox[gi*4+1];
            float gw = g_gtbox[gi*4+2], gh = g_gtbox[gi*4+3];
            float tlx = fmaxf(bb.x - bb.z*0.5f, gx - gw*0.5f);
            float tly = fmaxf(bb.y - bb.w*0.5f, gy - gh*0.5f);
            float brx = fminf(bb.x + bb.z*0.5f, gx + gw*0.5f);
            float bry = fminf(bb.y + bb.w*0.5f, gy + gh*0.5f);
            float en  = (tlx < brx && tly < bry) ? 1.f : 0.f;
            float inter = fmaxf(brx - tlx, 0.f) * fmaxf(bry - tly, 0.f) * en;
            float uni = bb.z*bb.w + gw*gh - inter + 1e-16f;
            float iou = inter / uni;
            liou = 1.f - iou * iou;

            int mcls = g_gtcls[gi];
            int hw, W, HW; float st;
            anchor_map(a, hw, W, HW, st);
            const float* src = (a < 6400) ? out0 : (a < 8000) ? out1 : out2;
            const float* p = src + (size_t)b * 85 * HW + hw;
            #pragma unroll 8
            for (int c = 0; c < NC_; c++) {
                float x = __ldg(&p[(5 + c) * HW]);
                float t = (c == mcls) ? piou : 0.f;
                lcls += bce_logit(x, t);
            }
        }
    }

    #pragma unroll
    for (int off = 16; off; off >>= 1) {
        liou += __shfl_down_sync(0xffffffffu, liou, off);
        lobj += __shfl_down_sync(0xffffffffu, lobj, off);
        lcls += __shfl_down_sync(0xffffffffu, lcls, off);
        lfg  += __shfl_down_sync(0xffffffffu, lfg,  off);
    }
    __shared__ float s4[8][4];
    int wid = threadIdx.x >> 5, lane = threadIdx.x & 31;
    if (lane == 0) { s4[wid][0] = liou; s4[wid][1] = lobj; s4[wid][2] = lcls; s4[wid][3] = lfg; }
    __syncthreads();
    if (threadIdx.x == 0) {
        float a0 = 0.f, a1 = 0.f, a2 = 0.f, a3 = 0.f;
        for (int i = 0; i < 8; i++) { a0 += s4[i][0]; a1 += s4[i][1]; a2 += s4[i][2]; a3 += s4[i][3]; }
        if (a0 != 0.f) atomicAdd(&g_accb[b][0], (double)a0);
        if (a1 != 0.f) atomicAdd(&g_accb[b][1], (double)a1);
        if (a2 != 0.f) atomicAdd(&g_accb[b][2], (double)a2);
        if (a3 != 0.f) atomicAdd(&g_accb[b][3], (double)a3);
    }
}

// ---------------- K6: finalize ----------------
__global__ void k_final(float* __restrict__ out) {
    if (threadIdx.x == 0) {
        double si = 0.0, so = 0.0, sc = 0.0, nf = 0.0;
        for (int b = 0; b < B_; b++) {
            si += g_accb[b][0]; so += g_accb[b][1];
            sc += g_accb[b][2]; nf += g_accb[b][3];
        }
        if (nf < 1.0) nf = 1.0;
        out[0] = (float)((5.0 * si + so + sc) / nf);
    }
}

// ---------------- launch ----------------
extern "C" void kernel_launch(void* const* d_in, const int* in_sizes, int n_in,
                              void* d_out, int out_size) {
    const float* out0   = (const float*)d_in[0];
    const float* out1   = (const float*)d_in[1];
    const float* out2   = (const float*)d_in[2];
    const float* labels = (const float*)d_in[3];
    float* out = (float*)d_out;

    k_gt<<<(B_*G_ + 127) / 128, 128>>>(labels);
    {
        dim3 g((NA_ + 255) / 256, B_);
        k_decode<<<g, 256>>>(out0, out1, out2);
    }
    {
        dim3 g(33, G_, B_);
        k_cost<<<g, 256>>>();
    }
    k_topk<<<(B_*G_*32 + 127) / 128, 128>>>();
    {
        dim3 g((NA_ + 255) / 256, B_);
        k_resolve<<<g, 256>>>(out0, out1, out2);
    }
    k_final<<<1, 32>>>(out);
}

// round 6
// speedup vs baseline: 1.7732x; 1.7732x over previous
#include <cuda_runtime.h>
#include <math.h>

#define B_  32
#define G_  50
#define NC_ 80
#define NA_ 8400

// ---------------- device scratch ----------------
__device__ float4        g_box [B_*NA_];
__device__ float         g_obj [B_*NA_];
__device__ float         g_Bo  [B_*NA_];
__device__ float         g_s   [B_*NA_];
__device__ int           g_flist[B_*NA_];
__device__ int           g_nfg [B_];
__device__ float         g_cost[B_*G_*NA_];
__device__ float         g_ioum[B_*G_*NA_];
__device__ float         g_gtbox[B_*G_*4];
__device__ int           g_gtcls[B_*G_];
__device__ unsigned char g_gtval[B_*G_];
__device__ float         g_thr [B_*G_];
__device__ double        g_accb[B_][4];

__device__ __forceinline__ void anchor_map(int a, int& hw, int& W, int& HW, float& st) {
    if (a < 6400)      { hw = a;        W = 80; HW = 6400; st = 8.f;  }
    else if (a < 8000) { hw = a - 6400; W = 40; HW = 1600; st = 16.f; }
    else               { hw = a - 8000; W = 20; HW = 400;  st = 32.f; }
}

__device__ __forceinline__ float bce_logit(float x, float y) {
    return fmaxf(x, 0.f) - x * y + log1pf(expf(-fabsf(x)));
}

// register-resident sorted lists (static indexing, branchless bubble)
__device__ __forceinline__ void ins_min10(float (&t)[10], float c) {
    if (c < t[9]) {
        t[9] = c;
        #pragma unroll
        for (int j = 9; j > 0; j--) {
            float lo = fminf(t[j-1], t[j]);
            float hi = fmaxf(t[j-1], t[j]);
            t[j-1] = lo; t[j] = hi;
        }
    }
}
__device__ __forceinline__ void ins_max10(float (&t)[10], float c) {
    if (c > t[9]) {
        t[9] = c;
        #pragma unroll
        for (int j = 9; j > 0; j--) {
            float hi = fmaxf(t[j-1], t[j]);
            float lo = fminf(t[j-1], t[j]);
            t[j-1] = hi; t[j] = lo;
        }
    }
}

// ---------------- K1: gt extraction + zero ----------------
__global__ void k_gt(const float* __restrict__ labels) {
    int i = blockIdx.x * blockDim.x + threadIdx.x;
    if (i < B_ * 4) ((double*)g_accb)[i] = 0.0;
    if (i < B_) g_nfg[i] = 0;
    if (i >= B_ * G_) return;
    const float* l = labels + i * 5;
    float c = l[0], x = l[1], y = l[2], w = l[3], h = l[4];
    g_gtval[i] = (c + x + y + w + h) > 0.f;
    g_gtbox[i*4+0] = x; g_gtbox[i*4+1] = y; g_gtbox[i*4+2] = w; g_gtbox[i*4+3] = h;
    g_gtcls[i] = (int)c;
}

// ---------------- K2: decode + fg + compact + s + obj softplus ----------------
__global__ void k_decode(const float* __restrict__ out0,
                         const float* __restrict__ out1,
                         const float* __restrict__ out2) {
    __shared__ float sgt[G_*4];
    __shared__ unsigned char sval[G_];
    int b = blockIdx.y;
    if (threadIdx.x < G_*4) sgt[threadIdx.x] = g_gtbox[b*G_*4 + threadIdx.x];
    if (threadIdx.x < G_)   sval[threadIdx.x] = g_gtval[b*G_ + threadIdx.x];
    __syncthreads();

    int a = blockIdx.x * blockDim.x + threadIdx.x;
    int lane = threadIdx.x & 31;
    float softplus_obj = 0.f;
    bool fg = false;
    int idx = b * NA_ + a;
    float Bo = 0.f;
    const float* p = nullptr;
    int HW = 0;

    if (a < NA_) {
        int hw, W; float st;
        anchor_map(a, hw, W, HW, st);
        const float* src = (a < 6400) ? out0 : (a < 8000) ? out1 : out2;
        p = src + (size_t)b * 85 * HW + hw;

        float tx = p[0], ty = p[HW], tw = p[2*HW], th = p[3*HW], to = p[4*HW];
        int h = hw / W, w = hw - h * W;
        g_box[idx] = make_float4((tx + (float)w) * st, (ty + (float)h) * st,
                                 expf(tw) * st, expf(th) * st);
        g_obj[idx] = to;
        Bo = 1.f + expf(-to);
        g_Bo[idx] = Bo;
        softplus_obj = fmaxf(to, 0.f) + log1pf(expf(-fabsf(to)));

        float cx = ((float)w + 0.5f) * st, cy = ((float)h + 0.5f) * st;
        float rs = 2.5f * st;
        for (int g = 0; g < G_; g++) {
            if (!sval[g]) continue;
            float gx = sgt[g*4], gy = sgt[g*4+1], gw = sgt[g*4+2], gh = sgt[g*4+3];
            bool ib = (cx > gx - 0.5f*gw) && (cx < gx + 0.5f*gw) &&
                      (cy > gy - 0.5f*gh) && (cy < gy + 0.5f*gh);
            bool ic = (fabsf(cx - gx) < rs) && (fabsf(cy - gy) < rs);
            fg |= (ib | ic);
        }
    }

    // warp-aggregated compaction append
    unsigned bal = __ballot_sync(0xffffffffu, fg);
    if (bal) {
        int leader = __ffs(bal) - 1;
        int base = 0;
        if (lane == leader) base = atomicAdd(&g_nfg[b], __popc(bal));
        base = __shfl_sync(0xffffffffu, base, leader);
        if (fg) g_flist[b*NA_ + base + __popc(bal & ((1u << lane) - 1))] = a;
    }

    if (fg) {
        float s0 = 0.f, s1 = 0.f;
        #pragma unroll 4
        for (int c = 0; c < NC_; c += 2) {
            float xc0 = p[(5 + c) * HW];
            float xc1 = p[(6 + c) * HW];
            float pv0 = rsqrtf((1.f + expf(-xc0)) * Bo);
            float pv1 = rsqrtf((1.f + expf(-xc1)) * Bo);
            pv0 = fminf(fmaxf(pv0, 1e-7f), 1.f - 1e-6f);
            pv1 = fminf(fmaxf(pv1, 1e-7f), 1.f - 1e-6f);
            s0 += log1pf(-pv0);
            s1 += log1pf(-pv1);
        }
        g_s[idx] = s0 + s1;
    }

    #pragma unroll
    for (int off = 16; off; off >>= 1)
        softplus_obj += __shfl_down_sync(0xffffffffu, softplus_obj, off);
    __shared__ float swsum[8];
    int wid = threadIdx.x >> 5;
    if (lane == 0) swsum[wid] = softplus_obj;
    __syncthreads();
    if (threadIdx.x == 0) {
        float t = 0.f;
        for (int i = 0; i < 8; i++) t += swsum[i];
        atomicAdd(&g_accb[b][1], (double)t);
    }
}

// ---------------- K3: fused cost + topk, block per (b,g) ----------------
#define TT_ 256
__global__ void k_costtopk(const float* __restrict__ out0,
                           const float* __restrict__ out1,
                           const float* __restrict__ out2) {
    int b = blockIdx.y, g = blockIdx.x;
    int gi = b * G_ + g;
    if (!g_gtval[gi]) return;
    int N = g_nfg[b];
    if (N == 0) return;

    float gx = g_gtbox[gi*4+0], gy = g_gtbox[gi*4+1];
    float gw = g_gtbox[gi*4+2], gh = g_gtbox[gi*4+3];
    int   cg = g_gtcls[gi];
    float gl = gx - gw*0.5f, gr = gx + gw*0.5f;
    float gt_ = gy - gh*0.5f, gbm = gy + gh*0.5f;
    float areag = gw * gh;
    int row = gi * NA_;

    float lc[10], li[10];
    #pragma unroll
    for (int i = 0; i < 10; i++) { lc[i] = 3.0e38f; li[i] = 0.f; }

    for (int f = threadIdx.x; f < N; f += TT_) {
        int a = g_flist[b*NA_ + f];
        int idx = b * NA_ + a;
        float4 bb = g_box[idx];

        float bz2 = bb.z * 0.5f, bw2 = bb.w * 0.5f;
        float tlx = fmaxf(gl,  bb.x - bz2);
        float tly = fmaxf(gt_, bb.y - bw2);
        float brx = fminf(gr,  bb.x + bz2);
        float bry = fminf(gbm, bb.y + bw2);
        float en  = (tlx < brx && tly < bry) ? 1.f : 0.f;
        float inter = (brx - tlx) * (bry - tly) * en;
        float iou = inter / (areag + bb.z*bb.w - inter + 1e-12f);

        int hw, W, HW; float st;
        anchor_map(a, hw, W, HW, st);
        int h = hw / W, w = hw - h * W;
        float cx = ((float)w + 0.5f) * st, cy = ((float)h + 0.5f) * st;
        bool ib = (cx > gl) && (cx < gr) && (cy > gt_) && (cy < gbm);
        float rs = 2.5f * st;
        bool ic = (fabsf(cx - gx) < rs) && (fabsf(cy - gy) < rs);
        bool geom = ib && ic;

        const float* src = (a < 6400) ? out0 : (a < 8000) ? out1 : out2;
        float xc = __ldg(&src[((size_t)b * 85 + 5 + cg) * HW + hw]);
        float pv = rsqrtf((1.f + expf(-xc)) * g_Bo[idx]);
        pv = fminf(fmaxf(pv, 1e-7f), 1.f - 1e-6f);
        float cls_cost = -logf(pv) + log1pf(-pv) - g_s[idx];
        float cost = cls_cost - 3.f * logf(iou + 1e-8f) + (geom ? 0.f : 100000.f);

        g_cost[row + f] = cost;
        g_ioum[row + f] = iou;
        ins_min10(lc, cost);
        ins_max10(li, iou);
    }

    // dump per-thread top-10s to shared
    __shared__ float sc[TT_*10];
    __shared__ float si[TT_*10];
    #pragma unroll
    for (int i = 0; i < 10; i++) {
        sc[threadIdx.x*10 + i] = lc[i];
        si[threadIdx.x*10 + i] = li[i];
    }
    __syncthreads();

    // warp 0: rescan 2560 candidates, then shuffle-merge
    if (threadIdx.x >= 32) return;
    int lane = threadIdx.x;
    #pragma unroll
    for (int i = 0; i < 10; i++) { lc[i] = 3.0e38f; li[i] = 0.f; }
    for (int i = lane; i < TT_*10; i += 32) {
        ins_min10(lc, sc[i]);
        ins_max10(li, si[i]);
    }

    // merge iou top-10 (desc) across lanes -> dyn_k (shift-advance per extraction)
    float isum = 0.f;
    for (int k = 0; k < 10; k++) {
        float bv = li[0]; int bl = lane;
        #pragma unroll
        for (int off = 16; off; off >>= 1) {
            float ov = __shfl_down_sync(0xffffffffu, bv, off);
            int   ol = __shfl_down_sync(0xffffffffu, bl, off);
            if (ov > bv || (ov == bv && ol < bl)) { bv = ov; bl = ol; }
        }
        bv = __shfl_sync(0xffffffffu, bv, 0);
        bl = __shfl_sync(0xffffffffu, bl, 0);
        if (lane == bl) {
            #pragma unroll
            for (int j = 0; j < 9; j++) li[j] = li[j+1];
            li[9] = -3.0e38f;
        }
        isum += bv;
    }
    int dynk = (int)isum;
    if (dynk < 1) dynk = 1;
    if (dynk > 10) dynk = 10;
    if (dynk > N) dynk = N;

    // merge cost smallest-10 (asc), pick (dynk-1)-th
    float thr = 0.f;
    for (int k = 0; k < 10; k++) {
        float bv = lc[0]; int bl = lane;
        #pragma unroll
        for (int off = 16; off; off >>= 1) {
            float ov = __shfl_down_sync(0xffffffffu, bv, off);
            int   ol = __shfl_down_sync(0xffffffffu, bl, off);
            if (ov < bv || (ov == bv && ol < bl)) { bv = ov; bl = ol; }
        }
        bv = __shfl_sync(0xffffffffu, bv, 0);
        bl = __shfl_sync(0xffffffffu, bl, 0);
        if (lane == bl) {
            #pragma unroll
            for (int j = 0; j < 9; j++) lc[j] = lc[j+1];
            lc[9] = 3.0e38f;
        }
        if (k == dynk - 1) thr = bv;
    }
    if (lane == 0) g_thr[gi] = thr;
}

// ---------------- K4: resolve + losses ----------------
__global__ void k_resolve(const float* __restrict__ out0,
                          const float* __restrict__ out1,
                          const float* __restrict__ out2) {
    __shared__ float sthr[G_];
    __shared__ unsigned char sval[G_];
    int b = blockIdx.y;
    if (threadIdx.x < G_) {
        sthr[threadIdx.x] = g_thr[b*G_ + threadIdx.x];
        sval[threadIdx.x] = g_gtval[b*G_ + threadIdx.x];
    }
    __syncthreads();

    int f = blockIdx.x * blockDim.x + threadIdx.x;
    float liou = 0.f, lobj = 0.f, lcls = 0.f, lfg = 0.f;
    if (f < g_nfg[b]) {
        int a = g_flist[b*NA_ + f];
        int idx = b * NA_ + a;
        unsigned long long mask = 0ull;
        int count = 0, bestg = 0;
        float minc = 3.4e38f;
        for (int g = 0; g < G_; g++) {
            if (!sval[g]) continue;
            float c = __ldg(&g_cost[(b*G_ + g) * NA_ + f]);
            if (c < minc) { minc = c; bestg = g; }
            if (c <= sthr[g]) { mask |= 1ull << g; count++; }
        }
        if (count > 1) mask &= (1ull << bestg);
        if (mask != 0ull) {
            int mg = __ffsll((long long)mask) - 1;
            float piou = 0.f;
            unsigned long long mm = mask;
            while (mm) {
                int g = __ffsll((long long)mm) - 1;
                mm &= mm - 1;
                piou += g_ioum[(b*G_ + g) * NA_ + f];
            }
            lfg = 1.f;
            lobj = -g_obj[idx];   // softplus part accumulated over all anchors in decode

            float4 bb = g_box[idx];
            int gi = b * G_ + mg;
            float gx = g_gtbox[gi*4+0], gy = g_gtbox[gi*4+1];
            float gw = g_gtbox[gi*4+2], gh = g_gtbox[gi*4+3];
            float tlx = fmaxf(bb.x - bb.z*0.5f, gx - gw*0.5f);
            float tly = fmaxf(bb.y - bb.w*0.5f, gy - gh*0.5f);
            float brx = fminf(bb.x + bb.z*0.5f, gx + gw*0.5f);
            float bry = fminf(bb.y + bb.w*0.5f, gy + gh*0.5f);
            float en  = (tlx < brx && tly < bry) ? 1.f : 0.f;
            float inter = fmaxf(brx - tlx, 0.f) * fmaxf(bry - tly, 0.f) * en;
            float uni = bb.z*bb.w + gw*gh - inter + 1e-16f;
            float iou = inter / uni;
            liou = 1.f - iou * iou;

            int mcls = g_gtcls[gi];
            int hw, W, HW; float st;
            anchor_map(a, hw, W, HW, st);
            const float* src = (a < 6400) ? out0 : (a < 8000) ? out1 : out2;
            const float* p = src + (size_t)b * 85 * HW + hw;
            #pragma unroll 4
            for (int c = 0; c < NC_; c++) {
                float x = __ldg(&p[(5 + c) * HW]);
                float t = (c == mcls) ? piou : 0.f;
                lcls += bce_logit(x, t);
            }
        }
    }

    #pragma unroll
    for (int off = 16; off; off >>= 1) {
        liou += __shfl_down_sync(0xffffffffu, liou, off);
        lobj += __shfl_down_sync(0xffffffffu, lobj, off);
        lcls += __shfl_down_sync(0xffffffffu, lcls, off);
        lfg  += __shfl_down_sync(0xffffffffu, lfg,  off);
    }
    __shared__ float s4[8][4];
    int wid = threadIdx.x >> 5, lane = threadIdx.x & 31;
    if (lane == 0) { s4[wid][0] = liou; s4[wid][1] = lobj; s4[wid][2] = lcls; s4[wid][3] = lfg; }
    __syncthreads();
    if (threadIdx.x == 0) {
        float a0 = 0.f, a1 = 0.f, a2 = 0.f, a3 = 0.f;
        for (int i = 0; i < 8; i++) { a0 += s4[i][0]; a1 += s4[i][1]; a2 += s4[i][2]; a3 += s4[i][3]; }
        if (a0 != 0.f) atomicAdd(&g_accb[b][0], (double)a0);
        if (a1 != 0.f) atomicAdd(&g_accb[b][1], (double)a1);
        if (a2 != 0.f) atomicAdd(&g_accb[b][2], (double)a2);
        if (a3 != 0.f) atomicAdd(&g_accb[b][3], (double)a3);
    }
}

// ---------------- K5: finalize ----------------
__global__ void k_final(float* __restrict__ out) {
    if (threadIdx.x == 0) {
        double si = 0.0, so = 0.0, sc = 0.0, nf = 0.0;
        for (int b = 0; b < B_; b++) {
            si += g_accb[b][0]; so += g_accb[b][1];
            sc += g_accb[b][2]; nf += g_accb[b][3];
        }
        if (nf < 1.0) nf = 1.0;
        out[0] = (float)((5.0 * si + so + sc) / nf);
    }
}

// ---------------- launch ----------------
extern "C" void kernel_launch(void* const* d_in, const int* in_sizes, int n_in,
                              void* d_out, int out_size) {
    const float* out0   = (const float*)d_in[0];
    const float* out1   = (const float*)d_in[1];
    const float* out2   = (const float*)d_in[2];
    const float* labels = (const float*)d_in[3];
    float* out = (float*)d_out;

    k_gt<<<(B_*G_ + 127) / 128, 128>>>(labels);
    {
        dim3 g((NA_ + 255) / 256, B_);
        k_decode<<<g, 256>>>(out0, out1, out2);
    }
    {
        dim3 g(G_, B_);
        k_costtopk<<<g, TT_>>>(out0, out1, out2);
    }
    {
        dim3 g((NA_ + 255) / 256, B_);
        k_resolve<<<g, 256>>>(out0, out1, out2);
    }
    k_final<<<1, 32>>>(out);
}

// round 7
// speedup vs baseline: 1.8874x; 1.0644x over previous
#include <cuda_runtime.h>
#include <math.h>

#define B_  32
#define G_  50
#define NC_ 80
#define NA_ 8400

// ---------------- device scratch ----------------
__device__ float4        g_box [B_*NA_];
__device__ float         g_obj [B_*NA_];
__device__ float         g_Bo  [B_*NA_];
__device__ float         g_s   [B_*NA_];   // sum_c log1p(-p_c)     (fg only)
__device__ float         g_sp  [B_*NA_];   // sum_c softplus(x_c)   (fg only)
__device__ int           g_flist[B_*NA_];
__device__ int           g_nfg [B_];
__device__ float         g_cost[B_*G_*NA_];
__device__ float         g_ioum[B_*G_*NA_];
__device__ float         g_gtbox[B_*G_*4];
__device__ int           g_gtcls[B_*G_];
__device__ unsigned char g_gtval[B_*G_];
__device__ float         g_thr [B_*G_];
__device__ double        g_accb[B_][4];

__device__ __forceinline__ void anchor_map(int a, int& hw, int& W, int& HW, float& st) {
    if (a < 6400)      { hw = a;        W = 80; HW = 6400; st = 8.f;  }
    else if (a < 8000) { hw = a - 6400; W = 40; HW = 1600; st = 16.f; }
    else               { hw = a - 8000; W = 20; HW = 400;  st = 32.f; }
}

// register-resident sorted lists (static indexing, branchless bubble)
__device__ __forceinline__ void ins_min10(float (&t)[10], float c) {
    if (c < t[9]) {
        t[9] = c;
        #pragma unroll
        for (int j = 9; j > 0; j--) {
            float lo = fminf(t[j-1], t[j]);
            float hi = fmaxf(t[j-1], t[j]);
            t[j-1] = lo; t[j] = hi;
        }
    }
}
__device__ __forceinline__ void ins_max10(float (&t)[10], float c) {
    if (c > t[9]) {
        t[9] = c;
        #pragma unroll
        for (int j = 9; j > 0; j--) {
            float hi = fmaxf(t[j-1], t[j]);
            float lo = fminf(t[j-1], t[j]);
            t[j-1] = hi; t[j] = lo;
        }
    }
}

// ---------------- K1: gt extraction + zero ----------------
__global__ void k_gt(const float* __restrict__ labels) {
    int i = blockIdx.x * blockDim.x + threadIdx.x;
    if (i < B_ * 4) ((double*)g_accb)[i] = 0.0;
    if (i < B_) g_nfg[i] = 0;
    if (i >= B_ * G_) return;
    const float* l = labels + i * 5;
    float c = l[0], x = l[1], y = l[2], w = l[3], h = l[4];
    g_gtval[i] = (c + x + y + w + h) > 0.f;
    g_gtbox[i*4+0] = x; g_gtbox[i*4+1] = y; g_gtbox[i*4+2] = w; g_gtbox[i*4+3] = h;
    g_gtcls[i] = (int)c;
}

// ---------------- K2: decode + fg + compact + obj softplus ----------------
__global__ void k_decode(const float* __restrict__ out0,
                         const float* __restrict__ out1,
                         const float* __restrict__ out2) {
    __shared__ float sgt[G_*4];
    __shared__ unsigned char sval[G_];
    int b = blockIdx.y;
    if (threadIdx.x < G_*4) sgt[threadIdx.x] = g_gtbox[b*G_*4 + threadIdx.x];
    if (threadIdx.x < G_)   sval[threadIdx.x] = g_gtval[b*G_ + threadIdx.x];
    __syncthreads();

    int a = blockIdx.x * blockDim.x + threadIdx.x;
    int lane = threadIdx.x & 31;
    float softplus_obj = 0.f;
    bool fg = false;

    if (a < NA_) {
        int idx = b * NA_ + a;
        int hw, W, HW; float st;
        anchor_map(a, hw, W, HW, st);
        const float* src = (a < 6400) ? out0 : (a < 8000) ? out1 : out2;
        const float* p = src + (size_t)b * 85 * HW + hw;

        float tx = p[0], ty = p[HW], tw = p[2*HW], th = p[3*HW], to = p[4*HW];
        int h = hw / W, w = hw - h * W;
        g_box[idx] = make_float4((tx + (float)w) * st, (ty + (float)h) * st,
                                 __expf(tw) * st, __expf(th) * st);
        g_obj[idx] = to;
        g_Bo[idx] = 1.f + __expf(-to);
        softplus_obj = fmaxf(to, 0.f) + __logf(1.f + __expf(-fabsf(to)));

        float cx = ((float)w + 0.5f) * st, cy = ((float)h + 0.5f) * st;
        float rs = 2.5f * st;
        for (int g = 0; g < G_; g++) {
            if (!sval[g]) continue;
            float gx = sgt[g*4], gy = sgt[g*4+1], gw = sgt[g*4+2], gh = sgt[g*4+3];
            bool ib = (cx > gx - 0.5f*gw) && (cx < gx + 0.5f*gw) &&
                      (cy > gy - 0.5f*gh) && (cy < gy + 0.5f*gh);
            bool ic = (fabsf(cx - gx) < rs) && (fabsf(cy - gy) < rs);
            fg |= (ib | ic);
        }
    }

    // warp-aggregated compaction append
    unsigned bal = __ballot_sync(0xffffffffu, fg);
    if (bal) {
        int leader = __ffs(bal) - 1;
        int base = 0;
        if (lane == leader) base = atomicAdd(&g_nfg[b], __popc(bal));
        base = __shfl_sync(0xffffffffu, base, leader);
        if (fg) g_flist[b*NA_ + base + __popc(bal & ((1u << lane) - 1))] = a;
    }

    #pragma unroll
    for (int off = 16; off; off >>= 1)
        softplus_obj += __shfl_down_sync(0xffffffffu, softplus_obj, off);
    __shared__ float swsum[8];
    int wid = threadIdx.x >> 5;
    if (lane == 0) swsum[wid] = softplus_obj;
    __syncthreads();
    if (threadIdx.x == 0) {
        float t = 0.f;
        for (int i = 0; i < 8; i++) t += swsum[i];
        atomicAdd(&g_accb[b][1], (double)t);
    }
}

// ---------------- K3: dense per-fg-anchor class stats (s, sp) ----------------
__global__ void k_stats(const float* __restrict__ out0,
                        const float* __restrict__ out1,
                        const float* __restrict__ out2) {
    int b = blockIdx.y;
    int f = blockIdx.x * blockDim.x + threadIdx.x;
    if (f >= g_nfg[b]) return;
    int a = g_flist[b*NA_ + f];
    int idx = b * NA_ + a;
    int hw, W, HW; float st;
    anchor_map(a, hw, W, HW, st);
    const float* src = (a < 6400) ? out0 : (a < 8000) ? out1 : out2;
    const float* p = src + ((size_t)b * 85 + 5) * HW + hw;
    float Bo = g_Bo[idx];

    float s = 0.f, splog = 0.f, xsum = 0.f;
    #pragma unroll 2
    for (int c = 0; c < NC_; c += 4) {
        float x0 = __ldg(&p[(c+0)*HW]);
        float x1 = __ldg(&p[(c+1)*HW]);
        float x2 = __ldg(&p[(c+2)*HW]);
        float x3 = __ldg(&p[(c+3)*HW]);
        float A0 = 1.f + __expf(-x0);
        float A1 = 1.f + __expf(-x1);
        float A2 = 1.f + __expf(-x2);
        float A3 = 1.f + __expf(-x3);
        float pv0 = fminf(fmaxf(rsqrtf(A0*Bo), 1e-7f), 1.f - 1e-6f);
        float pv1 = fminf(fmaxf(rsqrtf(A1*Bo), 1e-7f), 1.f - 1e-6f);
        float pv2 = fminf(fmaxf(rsqrtf(A2*Bo), 1e-7f), 1.f - 1e-6f);
        float pv3 = fminf(fmaxf(rsqrtf(A3*Bo), 1e-7f), 1.f - 1e-6f);
        s     += __logf(((1.f-pv0)*(1.f-pv1)) * ((1.f-pv2)*(1.f-pv3)));
        splog += __logf((A0*A1) * (A2*A3));
        xsum  += (x0 + x1) + (x2 + x3);
    }
    g_s[idx]  = s;
    g_sp[idx] = xsum + splog;   // sum softplus(x_c) = sum x_c + sum log(1+e^-x)
}

// ---------------- K4: fused cost + topk, block per (b,g) ----------------
#define TT_ 256
__global__ void k_costtopk(const float* __restrict__ out0,
                           const float* __restrict__ out1,
                           const float* __restrict__ out2) {
    int b = blockIdx.y, g = blockIdx.x;
    int gi = b * G_ + g;
    if (!g_gtval[gi]) return;
    int N = g_nfg[b];
    if (N == 0) return;

    float gx = g_gtbox[gi*4+0], gy = g_gtbox[gi*4+1];
    float gw = g_gtbox[gi*4+2], gh = g_gtbox[gi*4+3];
    int   cg = g_gtcls[gi];
    float gl = gx - gw*0.5f, gr = gx + gw*0.5f;
    float gt_ = gy - gh*0.5f, gbm = gy + gh*0.5f;
    float areag = gw * gh;
    int row = gi * NA_;

    float lc[10], li[10];
    #pragma unroll
    for (int i = 0; i < 10; i++) { lc[i] = 3.0e38f; li[i] = 0.f; }

    for (int f = threadIdx.x; f < N; f += TT_) {
        int a = g_flist[b*NA_ + f];
        int idx = b * NA_ + a;
        float4 bb = g_box[idx];

        float bz2 = bb.z * 0.5f, bw2 = bb.w * 0.5f;
        float tlx = fmaxf(gl,  bb.x - bz2);
        float tly = fmaxf(gt_, bb.y - bw2);
        float brx = fminf(gr,  bb.x + bz2);
        float bry = fminf(gbm, bb.y + bw2);
        float en  = (tlx < brx && tly < bry) ? 1.f : 0.f;
        float inter = (brx - tlx) * (bry - tly) * en;
        float iou = inter / (areag + bb.z*bb.w - inter + 1e-12f);

        int hw, W, HW; float st;
        anchor_map(a, hw, W, HW, st);
        int h = hw / W, w = hw - h * W;
        float cx = ((float)w + 0.5f) * st, cy = ((float)h + 0.5f) * st;
        bool ib = (cx > gl) && (cx < gr) && (cy > gt_) && (cy < gbm);
        float rs = 2.5f * st;
        bool ic = (fabsf(cx - gx) < rs) && (fabsf(cy - gy) < rs);
        bool geom = ib && ic;

        const float* src = (a < 6400) ? out0 : (a < 8000) ? out1 : out2;
        float xc = __ldg(&src[((size_t)b * 85 + 5 + cg) * HW + hw]);
        float pv = rsqrtf((1.f + __expf(-xc)) * g_Bo[idx]);
        pv = fminf(fmaxf(pv, 1e-7f), 1.f - 1e-6f);
        // cost = log((1-pv)/pv) - s - 3*log(iou+1e-8) + penalty
        float t = iou + 1e-8f;
        float cost = __logf((1.f - pv) / (pv * t * t * t)) - g_s[idx]
                   + (geom ? 0.f : 100000.f);

        g_cost[row + f] = cost;
        g_ioum[row + f] = iou;
        ins_min10(lc, cost);
        ins_max10(li, iou);
    }

    __shared__ float sc[TT_*10];
    __shared__ float si[TT_*10];
    #pragma unroll
    for (int i = 0; i < 10; i++) {
        sc[threadIdx.x*10 + i] = lc[i];
        si[threadIdx.x*10 + i] = li[i];
    }
    __syncthreads();

    if (threadIdx.x >= 32) return;
    int lane = threadIdx.x;
    #pragma unroll
    for (int i = 0; i < 10; i++) { lc[i] = 3.0e38f; li[i] = 0.f; }
    for (int i = lane; i < TT_*10; i += 32) {
        ins_min10(lc, sc[i]);
        ins_max10(li, si[i]);
    }

    float isum = 0.f;
    for (int k = 0; k < 10; k++) {
        float bv = li[0]; int bl = lane;
        #pragma unroll
        for (int off = 16; off; off >>= 1) {
            float ov = __shfl_down_sync(0xffffffffu, bv, off);
            int   ol = __shfl_down_sync(0xffffffffu, bl, off);
            if (ov > bv || (ov == bv && ol < bl)) { bv = ov; bl = ol; }
        }
        bv = __shfl_sync(0xffffffffu, bv, 0);
        bl = __shfl_sync(0xffffffffu, bl, 0);
        if (lane == bl) {
            #pragma unroll
            for (int j = 0; j < 9; j++) li[j] = li[j+1];
            li[9] = -3.0e38f;
        }
        isum += bv;
    }
    int dynk = (int)isum;
    if (dynk < 1) dynk = 1;
    if (dynk > 10) dynk = 10;
    if (dynk > N) dynk = N;

    float thr = 0.f;
    for (int k = 0; k < 10; k++) {
        float bv = lc[0]; int bl = lane;
        #pragma unroll
        for (int off = 16; off; off >>= 1) {
            float ov = __shfl_down_sync(0xffffffffu, bv, off);
            int   ol = __shfl_down_sync(0xffffffffu, bl, off);
            if (ov < bv || (ov == bv && ol < bl)) { bv = ov; bl = ol; }
        }
        bv = __shfl_sync(0xffffffffu, bv, 0);
        bl = __shfl_sync(0xffffffffu, bl, 0);
        if (lane == bl) {
            #pragma unroll
            for (int j = 0; j < 9; j++) lc[j] = lc[j+1];
            lc[9] = 3.0e38f;
        }
        if (k == dynk - 1) thr = bv;
    }
    if (lane == 0) g_thr[gi] = thr;
}

// ---------------- K5: resolve (warp per fg anchor) + losses ----------------
#define RW_ 8
__global__ void k_resolve(const float* __restrict__ out0,
                          const float* __restrict__ out1,
                          const float* __restrict__ out2) {
    int b = blockIdx.y;
    int wid = threadIdx.x >> 5, lane = threadIdx.x & 31;
    int f = blockIdx.x * RW_ + wid;
    int nfg = g_nfg[b];
    bool active = (f < nfg);

    float liou = 0.f, lobj = 0.f, lcls = 0.f, lfg = 0.f;

    if (active) {
        int a = g_flist[b*NA_ + f];
        int idx = b * NA_ + a;

        int g0 = lane, g1 = lane + 32;
        bool v0 = g_gtval[b*G_ + g0];
        bool v1 = (g1 < G_) ? (g_gtval[b*G_ + g1] != 0) : false;
        float c0 = v0 ? __ldg(&g_cost[(b*G_ + g0) * NA_ + f]) : 3.4e38f;
        float c1 = v1 ? __ldg(&g_cost[(b*G_ + g1) * NA_ + f]) : 3.4e38f;
        float t0 = v0 ? g_thr[b*G_ + g0] : 0.f;
        float t1 = v1 ? g_thr[b*G_ + g1] : 0.f;
        bool m0 = v0 && (c0 <= t0);
        bool m1 = v1 && (c1 <= t1);
        int count = __popc(__ballot_sync(0xffffffffu, m0))
                  + __popc(__ballot_sync(0xffffffffu, m1));

        // argmin cost over valid gts (smallest g on ties)
        float cmin = fminf(c0, c1);
        int   gmin = (c0 <= c1) ? g0 : g1;
        #pragma unroll
        for (int off = 16; off; off >>= 1) {
            float ov = __shfl_xor_sync(0xffffffffu, cmin, off);
            int   og = __shfl_xor_sync(0xffffffffu, gmin, off);
            if (ov < cmin || (ov == cmin && og < gmin)) { cmin = ov; gmin = og; }
        }

        if (count > 1) {
            m0 = m0 && (g0 == gmin);
            m1 = m1 && (g1 == gmin);
        }
        unsigned fb0 = __ballot_sync(0xffffffffu, m0);
        unsigned fb1 = __ballot_sync(0xffffffffu, m1);
        bool fgfin = (fb0 | fb1) != 0u;

        if (fgfin) {
            int mg = fb0 ? (__ffs(fb0) - 1) : (32 + __ffs(fb1) - 1);

            float io = 0.f;
            if (m0) io += __ldg(&g_ioum[(b*G_ + g0) * NA_ + f]);
            if (m1) io += __ldg(&g_ioum[(b*G_ + g1) * NA_ + f]);
            #pragma unroll
            for (int off = 16; off; off >>= 1)
                io += __shfl_xor_sync(0xffffffffu, io, off);
            float piou = io;

            // owner lane computes losses
            if (lane == (mg & 31)) {
                int gi = b * G_ + mg;
                float4 bb = g_box[idx];
                float gx = g_gtbox[gi*4+0], gy = g_gtbox[gi*4+1];
                float gw = g_gtbox[gi*4+2], gh = g_gtbox[gi*4+3];
                float tlx = fmaxf(bb.x - bb.z*0.5f, gx - gw*0.5f);
                float tly = fmaxf(bb.y - bb.w*0.5f, gy - gh*0.5f);
                float brx = fminf(bb.x + bb.z*0.5f, gx + gw*0.5f);
                float bry = fminf(bb.y + bb.w*0.5f, gy + gh*0.5f);
                float en  = (tlx < brx && tly < bry) ? 1.f : 0.f;
                float inter = fmaxf(brx - tlx, 0.f) * fmaxf(bry - tly, 0.f) * en;
                float uni = bb.z*bb.w + gw*gh - inter + 1e-16f;
                float iou = inter / uni;
                liou = 1.f - iou * iou;
                lfg  = 1.f;
                lobj = -g_obj[idx];   // softplus(obj) accumulated in decode

                int mcls = g_gtcls[gi];
                int hw, W, HW; float st;
                anchor_map(a, hw, W, HW, st);
                const float* src = (a < 6400) ? out0 : (a < 8000) ? out1 : out2;
                float xm = __ldg(&src[((size_t)b * 85 + 5 + mcls) * HW + hw]);
                lcls = g_sp[idx] - xm * piou;
            }
        }
    }

    // block reduce 4 floats
    #pragma unroll
    for (int off = 16; off; off >>= 1) {
        liou += __shfl_down_sync(0xffffffffu, liou, off);
        lobj += __shfl_down_sync(0xffffffffu, lobj, off);
        lcls += __shfl_down_sync(0xffffffffu, lcls, off);
        lfg  += __shfl_down_sync(0xffffffffu, lfg,  off);
    }
    __shared__ float s4[RW_][4];
    if (lane == 0) { s4[wid][0] = liou; s4[wid][1] = lobj; s4[wid][2] = lcls; s4[wid][3] = lfg; }
    __syncthreads();
    if (threadIdx.x == 0) {
        float a0 = 0.f, a1 = 0.f, a2 = 0.f, a3 = 0.f;
        for (int i = 0; i < RW_; i++) { a0 += s4[i][0]; a1 += s4[i][1]; a2 += s4[i][2]; a3 += s4[i][3]; }
        if (a0 != 0.f) atomicAdd(&g_accb[b][0], (double)a0);
        if (a1 != 0.f) atomicAdd(&g_accb[b][1], (double)a1);
        if (a2 != 0.f) atomicAdd(&g_accb[b][2], (double)a2);
        if (a3 != 0.f) atomicAdd(&g_accb[b][3], (double)a3);
    }
}

// ---------------- K6: finalize ----------------
__global__ void k_final(float* __restrict__ out) {
    if (threadIdx.x == 0) {
        double si = 0.0, so = 0.0, sc = 0.0, nf = 0.0;
        for (int b = 0; b < B_; b++) {
            si += g_accb[b][0]; so += g_accb[b][1];
            sc += g_accb[b][2]; nf += g_accb[b][3];
        }
        if (nf < 1.0) nf = 1.0;
        out[0] = (float)((5.0 * si + so + sc) / nf);
    }
}

// ---------------- launch ----------------
extern "C" void kernel_launch(void* const* d_in, const int* in_sizes, int n_in,
                              void* d_out, int out_size) {
    const float* out0   = (const float*)d_in[0];
    const float* out1   = (const float*)d_in[1];
    const float* out2   = (const float*)d_in[2];
    const float* labels = (const float*)d_in[3];
    float* out = (float*)d_out;

    k_gt<<<(B_*G_ + 127) / 128, 128>>>(labels);
    {
        dim3 g((NA_ + 255) / 256, B_);
        k_decode<<<g, 256>>>(out0, out1, out2);
    }
    {
        dim3 g((NA_ + 255) / 256, B_);
        k_stats<<<g, 256>>>(out0, out1, out2);
    }
    {
        dim3 g(G_, B_);
        k_costtopk<<<g, TT_>>>(out0, out1, out2);
    }
    {
        dim3 g((NA_ + RW_ - 1) / RW_, B_);
        k_resolve<<<g, 256>>>(out0, out1, out2);
    }
    k_final<<<1, 32>>>(out);
}